// round 15
// baseline (speedup 1.0000x reference)
#include <cuda_runtime.h>
#include <cstdint>
#include <math.h>

#define SEQ   2048
#define BATCH 64
#define INP   256
#define HID   256

typedef unsigned long long ull;

// ---------- packed f32x2 helpers (Blackwell FFMA2 path, PTX-only) ----------
__device__ __forceinline__ void ffma2(ull& d, ull a, ull b) {
    asm("fma.rn.f32x2 %0, %1, %2, %0;" : "+l"(d) : "l"(a), "l"(b));
}
__device__ __forceinline__ ull pk(float a, float b) {
    ull r; asm("mov.b64 %0, {%1, %2};" : "=l"(r) : "f"(a), "f"(b)); return r;
}
__device__ __forceinline__ ull pku(unsigned a, unsigned b) {
    ull r; asm("mov.b64 %0, {%1, %2};" : "=l"(r) : "r"(a), "r"(b)); return r;
}
__device__ __forceinline__ float2 unpk(ull v) {
    float x, y; asm("mov.b64 {%0, %1}, %2;" : "=f"(x), "=f"(y) : "l"(v));
    return make_float2(x, y);
}
__device__ __forceinline__ unsigned smem_u32(const void* p) {
    unsigned a;
    asm("{ .reg .u64 t; cvta.to.shared.u64 t, %1; cvt.u32.u64 %0, t; }"
        : "=r"(a) : "l"(p));
    return a;
}
__device__ __forceinline__ unsigned mapa_peer(unsigned local_addr, unsigned peer) {
    unsigned r;
    asm("mapa.shared::cluster.u32 %0, %1, %2;" : "=r"(r) : "r"(local_addr), "r"(peer));
    return r;
}
// Branch-free tanh: 1 - 2/(e^{2x}+1). ex2/rcp approx, abs err ~1e-7.
__device__ __forceinline__ float fast_tanh(float x) {
    float e;
    asm("ex2.approx.ftz.f32 %0, %1;" : "=f"(e) : "f"(x * 2.8853900817779268f));
    float r;
    asm("rcp.approx.ftz.f32 %0, %1;" : "=f"(r) : "f"(e + 1.0f));
    return fmaf(-2.0f, r, 1.0f);
}

// =====================================================================
// Phase 1: xp[t,b,h] = x[t,b]·W_ih[h] + b_ih[h] + b_hh[h]  (unchanged)
// =====================================================================
__global__ __launch_bounds__(256) void xp_gemm_kernel(
    const float* __restrict__ x,
    const float* __restrict__ Wih,
    const float* __restrict__ bih,
    const float* __restrict__ bhh,
    float* __restrict__ out)
{
    __shared__ float Xs[32][68];
    __shared__ float Ws[32][257];

    const int t   = blockIdx.x;
    const int tid = threadIdx.x;
    const int tn  = tid & 31;
    const int tm  = tid >> 5;
    const int m0  = tm * 8;

    const float* xt = x + (size_t)t * BATCH * INP;

    ull acc[8][4];
    #pragma unroll
    for (int u = 0; u < 8; ++u)
        #pragma unroll
        for (int v = 0; v < 4; ++v) acc[u][v] = 0ull;

    for (int kc = 0; kc < INP; kc += 32) {
        #pragma unroll
        for (int r = 0; r < 2; ++r) {
            int idx = tid + 256 * r;
            int m   = idx >> 3;
            int k4  = (idx & 7) * 4;
            float4 v = *(const float4*)(xt + (size_t)m * INP + kc + k4);
            Xs[k4 + 0][m] = v.x; Xs[k4 + 1][m] = v.y;
            Xs[k4 + 2][m] = v.z; Xs[k4 + 3][m] = v.w;
        }
        #pragma unroll
        for (int r = 0; r < 8; ++r) {
            int idx = tid + 256 * r;
            int h   = idx >> 3;
            int k4  = (idx & 7) * 4;
            float4 v = *(const float4*)(Wih + (size_t)h * INP + kc + k4);
            Ws[k4 + 0][h] = v.x; Ws[k4 + 1][h] = v.y;
            Ws[k4 + 2][h] = v.z; Ws[k4 + 3][h] = v.w;
        }
        __syncthreads();

        #pragma unroll
        for (int k = 0; k < 32; ++k) {
            float4 a0 = *(const float4*)&Xs[k][m0];
            float4 a1 = *(const float4*)&Xs[k][m0 + 4];
            ull ap[8];
            ap[0] = pk(a0.x, a0.x); ap[1] = pk(a0.y, a0.y);
            ap[2] = pk(a0.z, a0.z); ap[3] = pk(a0.w, a0.w);
            ap[4] = pk(a1.x, a1.x); ap[5] = pk(a1.y, a1.y);
            ap[6] = pk(a1.z, a1.z); ap[7] = pk(a1.w, a1.w);

            float w[8];
            #pragma unroll
            for (int v = 0; v < 8; ++v) w[v] = Ws[k][tn + 32 * v];

            #pragma unroll
            for (int v2 = 0; v2 < 4; ++v2) {
                ull wp = pk(w[2 * v2], w[2 * v2 + 1]);
                #pragma unroll
                for (int u = 0; u < 8; ++u)
                    ffma2(acc[u][v2], wp, ap[u]);
            }
        }
        __syncthreads();
    }

    float ba[4], bb[4];
    #pragma unroll
    for (int v2 = 0; v2 < 4; ++v2) {
        int hA = tn + 64 * v2, hB = hA + 32;
        ba[v2] = bih[hA] + bhh[hA];
        bb[v2] = bih[hB] + bhh[hB];
    }
    float* ot = out + (size_t)t * BATCH * HID;
    #pragma unroll
    for (int u = 0; u < 8; ++u) {
        float* row = ot + (size_t)(m0 + u) * HID;
        #pragma unroll
        for (int v2 = 0; v2 < 4; ++v2) {
            float2 s = unpk(acc[u][v2]);
            row[tn + 64 * v2]      = s.x + ba[v2];
            row[tn + 64 * v2 + 32] = s.y + bb[v2];
        }
    }
}

// =====================================================================
// Phase 2: serial scan, v13 — sender-side matvec, reduced-partial xfer.
// Cluster {2b,2b+1}; rank r finalizes rows [128r,+128). Per step, only
// 2 reduced partials per row cross CTAs (transit overlaps g0's matvec).
// 512 threads, group = tid>>7, jj = tid&127, kh = group&1:
//   g0 (w0-3) : my row jj, k=[128r,+64)      -> finalize (poll 3 pairs)
//   g1 (w4-7) : my row jj, k=[128r+64,+64)   -> local partial pair
//   s0 (w8-11): PEER row jj, k=[128r,+64)    -> pair to peer (DSMEM)
//   s1 (w12-15): PEER row jj, k=[128r+64,+64)-> pair to peer
// All groups read h_{t-1} from local hbuf (senders use only local h!).
// Pairs are {f32 partial, seq=t+1} u64 (single-copy atomic; seq
// validates — no fences/mbarriers). One bar.sync per step orders
// hbuf writes + pair slot reuse. Senders in warps 8-15 (hi-wid
// arbiter priority -> sends launch earliest).
// =====================================================================
__global__ __launch_bounds__(512, 1) __cluster_dims__(2, 1, 1)
void rnn_scan_kernel(
    const float* __restrict__ Whh,  // [HID][HID]
    float* __restrict__ out)        // in: xp, out: h   [SEQ][BATCH][HID]
{
    __shared__ float hbuf[2][128];                 // local rows' h by parity
    __shared__ alignas(16) ull lpair[2][128];      // g1 partials [par][jj]
    __shared__ alignas(16) ull rpair[2][2][128];   // peer partials [par][s][jj]

    const int bidx  = blockIdx.x;
    const int b     = bidx >> 1;
    const int r     = bidx & 1;            // cluster rank
    const int tid   = threadIdx.x;
    const int jj    = tid & 127;           // row index within a half
    const int group = tid >> 7;            // 0=g0 1=g1 2=s0 3=s1
    const int kh    = group & 1;           // k sub-half within my k-half

    // row whose partial I compute: local rows for g0/g1, peer rows for s0/s1
    const int wrow_idx = (group < 2) ? (128 * r + jj) : (128 * (1 - r) + jj);

    // ---- register-resident W: W_hh[wrow_idx][128r + 64*kh + 0..63] ----
    ull wreg[32];
    {
        const float* wrow = Whh + (size_t)wrow_idx * HID + 128 * r + 64 * kh;
        #pragma unroll
        for (int p = 0; p < 32; ++p)
            wreg[p] = *(const ull*)(wrow + 2 * p);
    }

    // ---- init smem ----
    if (tid < 256) ((float*)hbuf)[tid] = 0.f;
    if (tid < 256) ((ull*)lpair)[tid] = 0ull;
    ((ull*)rpair)[tid] = 0ull;
    __syncthreads();
    asm volatile("barrier.cluster.arrive.aligned;" ::: "memory");
    asm volatile("barrier.cluster.wait.aligned;"   ::: "memory");

    const unsigned peer     = (unsigned)(r ^ 1);
    const unsigned lpair_l  = smem_u32(lpair);
    const unsigned rpair_l  = smem_u32(rpair);
    const unsigned peer_rp  = mapa_peer(rpair_l, peer);

    const size_t stride = (size_t)BATCH * HID;
    float* col = out + (size_t)b * HID + (128 * r + jj);   // g0's row column

    // xp prefetch queue, depth 2 (g0 holds it)
    float xq0 = 0.f, xq1 = 0.f;
    if (group == 0) {
        xq0 = __ldcg(col);
        xq1 = __ldcg(col + stride);
    }

    for (int t = 0; t < SEQ; ++t) {
        const unsigned sp = (unsigned)(t & 1);   // this step's pair parity
        const unsigned rp = sp ^ 1u;             // h_{t-1} parity
        const unsigned T1 = (unsigned)(t + 1);

        // g0: hoist next xp load (independent of everything)
        float xq2 = 0.f;
        if (group == 0 && t + 2 < SEQ)
            xq2 = __ldcg(col + (size_t)(t + 2) * stride);

        // ---- uniform matvec: 64 k-values from LOCAL hbuf ----
        const ulonglong2* h2 = (const ulonglong2*)&hbuf[rp][64 * kh];
        ull a0 = 0ull, a1 = 0ull, a2 = 0ull, a3 = 0ull;
        #pragma unroll
        for (int q = 0; q < 16; ++q) {
            ulonglong2 h = h2[q];
            if (q & 1) { ffma2(a2, wreg[2 * q],     h.x);
                         ffma2(a3, wreg[2 * q + 1], h.y); }
            else       { ffma2(a0, wreg[2 * q],     h.x);
                         ffma2(a1, wreg[2 * q + 1], h.y); }
        }
        float2 s0 = unpk(a0), s1 = unpk(a1), s2 = unpk(a2), s3 = unpk(a3);
        float part = ((s0.x + s0.y) + (s1.x + s1.y))
                   + ((s2.x + s2.y) + (s3.x + s3.y));

        if (group >= 2) {
            // ---- sender: ship reduced partial of peer row jj ----
            ull pv = pku(__float_as_uint(part), T1);
            asm volatile("st.shared::cluster.u64 [%0], %1;"
                         :: "r"(peer_rp + sp * 2048u + (unsigned)kh * 1024u
                                        + (unsigned)jj * 8u),
                            "l"(pv) : "memory");
        } else if (group == 1) {
            // ---- local co-partial pair ----
            ull pv = pku(__float_as_uint(part), T1);
            asm volatile("st.volatile.shared.u64 [%0], %1;"
                         :: "r"(lpair_l + sp * 1024u + (unsigned)jj * 8u),
                            "l"(pv) : "memory");
        } else {
            // ---- g0 finalizes: poll 1 local + 2 remote pairs ----
            const unsigned la = lpair_l + sp * 1024u + (unsigned)jj * 8u;
            const unsigned ra = rpair_l + sp * 2048u + (unsigned)jj * 8u;
            ull v1, v2, v3;
            unsigned ok;
            do {
                asm volatile("ld.volatile.shared.u64 %0, [%1];"
                             : "=l"(v1) : "r"(la) : "memory");
                asm volatile("ld.volatile.shared.u64 %0, [%1];"
                             : "=l"(v2) : "r"(ra) : "memory");
                asm volatile("ld.volatile.shared.u64 %0, [%1];"
                             : "=l"(v3) : "r"(ra + 1024u) : "memory");
                ok = ((unsigned)(v1 >> 32) == T1)
                   & ((unsigned)(v2 >> 32) == T1)
                   & ((unsigned)(v3 >> 32) == T1);
            } while (!ok);

            float sum = (part + __uint_as_float((unsigned)v1))
                      + (__uint_as_float((unsigned)v2)
                      +  __uint_as_float((unsigned)v3));
            float val = fast_tanh(xq0 + sum);

            hbuf[sp][jj] = val;              // h_t (ordered by bar.sync)
            col[(size_t)t * stride] = val;   // h_t -> gmem
            xq0 = xq1;
            xq1 = xq2;
        }

        __syncthreads();   // orders hbuf + pair-slot reuse; one per step
    }

    asm volatile("barrier.cluster.arrive.aligned;" ::: "memory");
    asm volatile("barrier.cluster.wait.aligned;"   ::: "memory");
}

// =====================================================================
extern "C" void kernel_launch(void* const* d_in, const int* in_sizes, int n_in,
                              void* d_out, int out_size) {
    const float* x   = (const float*)d_in[0];  // [SEQ][BATCH][INP]
    const float* Wih = (const float*)d_in[1];  // [HID][INP]
    const float* Whh = (const float*)d_in[2];  // [HID][HID]
    const float* bih = (const float*)d_in[3];  // [HID]
    const float* bhh = (const float*)d_in[4];  // [HID]
    float* out = (float*)d_out;                // [SEQ][BATCH][HID]

    xp_gemm_kernel<<<SEQ, 256>>>(x, Wih, bih, bhh, out);
    rnn_scan_kernel<<<2 * BATCH, 512>>>(Whh, out);
}